// round 2
// baseline (speedup 1.0000x reference)
#include <cuda_runtime.h>

#define NB 8
#define NSEQ 1024
#define NH 8
#define HD 64
#define CDIM 512

__device__ float g_q[NB*NH*NSEQ*HD];
__device__ float g_k[NB*NH*NSEQ*HD];
__device__ float g_v[NB*NH*NSEQ*HD];
__device__ float g_s[(size_t)NB*NH*NSEQ*NSEQ];   // 256 MB
__device__ float g_oh[NB*NSEQ*CDIM];

#define EPI_QKV  0
#define EPI_DOTS 1
#define EPI_PV   2
#define EPI_OUT  3

template<int EPI, int BN, int TN, bool TRANSB, int LDA_, int LDB_, int KD_>
__global__ __launch_bounds__(256)
void sgemm_k(const float* __restrict__ Ain, const float* __restrict__ Bin,
             const float* __restrict__ bias, float* __restrict__ Cout, float scale)
{
    constexpr int BM = 128, BK = 8, KT = KD_ / BK;
    __shared__ float As[BK][BM];
    __shared__ float Bs[BK][BN];

    const int t  = threadIdx.x;
    const int tx = t & 15;
    const int ty = t >> 4;
    const int m0 = blockIdx.y * BM;
    const int n0 = blockIdx.x * BN;
    const int z  = blockIdx.z;

    const float* Ap;
    const float* Bp;
    if      constexpr (EPI == EPI_QKV)  { Ap = Ain;                     Bp = Bin; }
    else if constexpr (EPI == EPI_DOTS) { Ap = g_q + (size_t)z*NSEQ*HD; Bp = g_k + (size_t)z*NSEQ*HD; }
    else if constexpr (EPI == EPI_PV)   { Ap = g_s + ((size_t)z << 20); Bp = g_v + (size_t)z*NSEQ*HD; }
    else                                { Ap = g_oh;                    Bp = Bin; }

    // A loader: 128 rows x 8 k, one float4/thread
    const int arow  = t >> 1;
    const int acolk = (t & 1) * 4;
    // B loader
    int brow, bcol; bool bact = true;
    if constexpr (TRANSB) { brow = t >> 1; bcol = (t & 1) * 4; }
    else {
        constexpr int BRD = BN / 4;
        brow = t / BRD; bcol = (t % BRD) * 4; bact = (t < BK * BRD);
    }

    float acc[8][TN];
    #pragma unroll
    for (int i = 0; i < 8; i++)
        #pragma unroll
        for (int j = 0; j < TN; j++) acc[i][j] = 0.f;

    float4 rA = make_float4(0,0,0,0), rB = make_float4(0,0,0,0);

    rA = *reinterpret_cast<const float4*>(Ap + (size_t)(m0 + arow) * LDA_ + acolk);
    if constexpr (TRANSB)
        rB = *reinterpret_cast<const float4*>(Bp + (size_t)(n0 + brow) * LDB_ + bcol);
    else if (bact)
        rB = *reinterpret_cast<const float4*>(Bp + (size_t)brow * LDB_ + n0 + bcol);

    As[acolk+0][arow]=rA.x; As[acolk+1][arow]=rA.y; As[acolk+2][arow]=rA.z; As[acolk+3][arow]=rA.w;
    if constexpr (TRANSB) {
        Bs[bcol+0][brow]=rB.x; Bs[bcol+1][brow]=rB.y; Bs[bcol+2][brow]=rB.z; Bs[bcol+3][brow]=rB.w;
    } else if (bact) {
        *reinterpret_cast<float4*>(&Bs[brow][bcol]) = rB;
    }
    __syncthreads();

    for (int kt = 0; kt < KT; kt++) {
        if (kt + 1 < KT) {
            const int k1 = (kt + 1) * BK;
            rA = *reinterpret_cast<const float4*>(Ap + (size_t)(m0 + arow) * LDA_ + k1 + acolk);
            if constexpr (TRANSB)
                rB = *reinterpret_cast<const float4*>(Bp + (size_t)(n0 + brow) * LDB_ + k1 + bcol);
            else if (bact)
                rB = *reinterpret_cast<const float4*>(Bp + (size_t)(k1 + brow) * LDB_ + n0 + bcol);
        }
        #pragma unroll
        for (int kk = 0; kk < BK; kk++) {
            float ar[8], br[TN];
            *reinterpret_cast<float4*>(&ar[0]) = *reinterpret_cast<const float4*>(&As[kk][ty*8]);
            *reinterpret_cast<float4*>(&ar[4]) = *reinterpret_cast<const float4*>(&As[kk][ty*8+4]);
            *reinterpret_cast<float4*>(&br[0]) = *reinterpret_cast<const float4*>(&Bs[kk][tx*TN]);
            if constexpr (TN == 8)
                *reinterpret_cast<float4*>(&br[4]) = *reinterpret_cast<const float4*>(&Bs[kk][tx*TN+4]);
            #pragma unroll
            for (int i = 0; i < 8; i++)
                #pragma unroll
                for (int j = 0; j < TN; j++)
                    acc[i][j] += ar[i] * br[j];
        }
        __syncthreads();
        if (kt + 1 < KT) {
            As[acolk+0][arow]=rA.x; As[acolk+1][arow]=rA.y; As[acolk+2][arow]=rA.z; As[acolk+3][arow]=rA.w;
            if constexpr (TRANSB) {
                Bs[bcol+0][brow]=rB.x; Bs[bcol+1][brow]=rB.y; Bs[bcol+2][brow]=rB.z; Bs[bcol+3][brow]=rB.w;
            } else if (bact) {
                *reinterpret_cast<float4*>(&Bs[brow][bcol]) = rB;
            }
            __syncthreads();
        }
    }

    #pragma unroll
    for (int i = 0; i < 8; i++) {
        const int r = m0 + ty*8 + i;
        #pragma unroll
        for (int j = 0; j < TN; j++) {
            const int c = n0 + tx*TN + j;
            const float v = acc[i][j];
            if constexpr (EPI == EPI_QKV) {
                const int part = c >> 9, rem = c & 511;
                const int h = rem >> 6, d = rem & 63;
                const int b = r >> 10, n = r & 1023;
                float* dst = (part == 0) ? g_q : (part == 1) ? g_k : g_v;
                dst[(((size_t)(b*NH + h))*NSEQ + n)*HD + d] = v;
            } else if constexpr (EPI == EPI_DOTS) {
                g_s[((size_t)z << 20) + (size_t)r*NSEQ + c] = v * scale;
            } else if constexpr (EPI == EPI_PV) {
                const int b = z >> 3, h = z & 7;
                g_oh[((size_t)(b*NSEQ + r))*CDIM + h*HD + c] = v;
            } else {
                Cout[(size_t)r*CDIM + c] = v + bias[c];
            }
        }
    }
}

// Fused: per (b,i) row — softmax over j per head, 8x8 head remix, LayerNorm over heads.
__global__ __launch_bounds__(256)
void softmax_remix_ln(const float* __restrict__ W,
                      const float* __restrict__ gamma,
                      const float* __restrict__ beta)
{
    __shared__ float s[NH][NSEQ];    // 32 KB
    __shared__ float w_s[64], g_s_[8], b_s_[8];

    const int t = threadIdx.x;
    const int bi = blockIdx.x;
    const int b = bi >> 10, i = bi & 1023;

    if (t < 64) w_s[t] = W[t];
    if (t >= 64 && t < 72) { g_s_[t-64] = gamma[t-64]; b_s_[t-64] = beta[t-64]; }

    // Phase 1: warp w handles head h=w
    const int wid = t >> 5, lid = t & 31;
    {
        const float* row = g_s + (((size_t)(b*NH + wid))*NSEQ + i)*NSEQ;
        float v[32];
        float m = -1e30f;
        #pragma unroll
        for (int u = 0; u < 32; u++) { v[u] = row[lid + 32*u]; m = fmaxf(m, v[u]); }
        #pragma unroll
        for (int o = 16; o > 0; o >>= 1) m = fmaxf(m, __shfl_xor_sync(0xffffffffu, m, o));
        float sum = 0.f;
        #pragma unroll
        for (int u = 0; u < 32; u++) { v[u] = __expf(v[u] - m); sum += v[u]; }
        #pragma unroll
        for (int o = 16; o > 0; o >>= 1) sum += __shfl_xor_sync(0xffffffffu, sum, o);
        const float inv = 1.f / sum;
        #pragma unroll
        for (int u = 0; u < 32; u++) s[wid][lid + 32*u] = v[u] * inv;
    }
    __syncthreads();

    // Phase 2: remix + LN per column j; write back in place
    #pragma unroll
    for (int u = 0; u < 4; u++) {
        const int j = t + 256*u;
        float a[8], mres[8];
        #pragma unroll
        for (int h = 0; h < 8; h++) a[h] = s[h][j];
        float mean = 0.f;
        #pragma unroll
        for (int g = 0; g < 8; g++) {
            float acc = 0.f;
            #pragma unroll
            for (int h = 0; h < 8; h++) acc += a[h] * w_s[h*8 + g];
            mres[g] = acc; mean += acc;
        }
        mean *= 0.125f;
        float var = 0.f;
        #pragma unroll
        for (int g = 0; g < 8; g++) { float d = mres[g] - mean; var += d*d; }
        var *= 0.125f;
        const float rstd = rsqrtf(var + 1e-5f);
        #pragma unroll
        for (int g = 0; g < 8; g++) {
            const float o = (mres[g] - mean) * rstd * g_s_[g] + b_s_[g];
            g_s[(((size_t)(b*NH + g))*NSEQ + i)*NSEQ + j] = o;
        }
    }
}

extern "C" void kernel_launch(void* const* d_in, const int* in_sizes, int n_in,
                              void* d_out, int out_size)
{
    const float* x      = (const float*)d_in[0];
    const float* w_qkv  = (const float*)d_in[1];
    const float* reattn = (const float*)d_in[2];
    const float* gamma  = (const float*)d_in[3];
    const float* beta   = (const float*)d_in[4];
    const float* w_out  = (const float*)d_in[5];
    const float* b_out  = (const float*)d_in[6];
    float* out = (float*)d_out;
    const float scale = 0.125f;  // 64^-0.5

    // 1) qkv = x @ w_qkv, scatter to g_q/g_k/g_v
    sgemm_k<EPI_QKV, 128, 8, false, 512, 1536, 512>
        <<<dim3(12, 64, 1), 256>>>(x, w_qkv, nullptr, nullptr, 1.f);
    // 2) dots = q @ k^T * scale (64 batches)
    sgemm_k<EPI_DOTS, 128, 8, true, 64, 64, 64>
        <<<dim3(8, 8, 64), 256>>>(nullptr, nullptr, nullptr, nullptr, scale);
    // 3) softmax + remix + LN (in place on g_s)
    softmax_remix_ln<<<NB*NSEQ, 256>>>(reattn, gamma, beta);
    // 4) out_h = attn @ v (64 batches)
    sgemm_k<EPI_PV, 64, 4, false, 1024, 64, 1024>
        <<<dim3(1, 8, 64), 256>>>(nullptr, nullptr, nullptr, nullptr, 1.f);
    // 5) out = g_oh @ w_out + b_out
    sgemm_k<EPI_OUT, 128, 8, false, 512, 512, 512>
        <<<dim3(4, 64, 1), 256>>>(nullptr, w_out, b_out, out, 1.f);
}